// round 10
// baseline (speedup 1.0000x reference)
#include <cuda_runtime.h>

#define BB 1024
#define LL 4096
#define DD 64
#define KK 64
#define NCHUNK 4
#define CROWS (LL / NCHUNK)       // 1024 rows per chunk
#define NTHREADS 256
#define NWARPS 8
#define WR (CROWS / NWARPS)       // 128 rows per warp
#define NTILES (WR / 8)           // 16 tiles of 8 rows
#define TILE_BYTES 2048

typedef unsigned long long u64;

__device__ int g_mask_mode;                 // 0=int32, 1=byte, 2=float32
__device__ u64 g_part[BB * NCHUNK * KK];    // 2 MB chunk-top64 scratch
__device__ int g_count[BB];                 // per-batch arrival counters (self-resetting)

// ---------------------------------------------------------------------------
__global__ void detect_mask_kernel(const unsigned int* __restrict__ m) {
    __shared__ int f_byte, f_float;
    int tid = threadIdx.x;
    if (tid == 0) { f_byte = 0; f_float = 0; }
    __syncthreads();
    unsigned int w = m[tid];
    if (w == 0x3F800000u) f_float = 1;
    else if (w > 1u)      f_byte = 1;
    __syncthreads();
    if (tid == 0) g_mask_mode = f_float ? 2 : (f_byte ? 1 : 0);
}

// ---- TMA bulk-copy helpers ------------------------------------------------
__device__ __forceinline__ void mbar_init(unsigned int mbar, unsigned int count) {
    asm volatile("mbarrier.init.shared.b64 [%0], %1;" :: "r"(mbar), "r"(count) : "memory");
}
__device__ __forceinline__ void mbar_expect_tx(unsigned int mbar, unsigned int bytes) {
    asm volatile("mbarrier.arrive.expect_tx.shared.b64 _, [%0], %1;" :: "r"(mbar), "r"(bytes) : "memory");
}
__device__ __forceinline__ void cp_bulk(unsigned int dst, const void* src,
                                        unsigned int bytes, unsigned int mbar) {
    asm volatile("cp.async.bulk.shared::cta.global.mbarrier::complete_tx::bytes [%0], [%1], %2, [%3];"
                 :: "r"(dst), "l"(src), "r"(bytes), "r"(mbar) : "memory");
}
__device__ __forceinline__ void mbar_wait(unsigned int mbar, unsigned int parity) {
    asm volatile(
        "{\n\t.reg .pred P;\n"
        "WAIT_%=:\n\t"
        "mbarrier.try_wait.parity.acquire.cta.shared::cta.b64 P, [%0], %1, 0x989680;\n\t"
        "@P bra.uni DONE_%=;\n\t"
        "bra.uni WAIT_%=;\n"
        "DONE_%=:\n\t}"
        :: "r"(mbar), "r"(parity) : "memory");
}

// ---------------------------------------------------------------------------
// Kernel A (fused): one CTA per (batch, chunk). Per-warp TMA bulk tile
// pipeline -> smem-transposed scoring -> warp top-64 -> CTA merge -> g_part;
// last-arriving chunk-CTA merges the batch, gathers rows, writes mask.
// ---------------------------------------------------------------------------
__global__ __launch_bounds__(NTHREADS) void gsu_score_kernel(
    const float* __restrict__ tgt,
    const float* __restrict__ seq,
    const void*  __restrict__ mraw,
    const float* __restrict__ W,
    float* __restrict__ out_emb,
    float* __restrict__ out_mask,
    int write_mask)
{
    __shared__ u64 keys[CROWS];                         // 8 KB
    __shared__ float4 tiles[NWARPS * 2 * 128];          // 32 KB (reused as merge buf)
    __shared__ float ts[DD];
    __shared__ float qs[DD];
    __shared__ unsigned char smask[CROWS];              // 1 KB
    __shared__ __align__(8) u64 mbars[NWARPS * 2];      // per-warp double-buffer barriers
    __shared__ int s_last;

    const int b   = blockIdx.x >> 2;
    const int c   = blockIdx.x & 3;
    const int tid = threadIdx.x;
    const int lane = tid & 31;
    const int warp = tid >> 5;

    const unsigned int mb0 = (unsigned int)__cvta_generic_to_shared(&mbars[warp * 2]);
    const unsigned int mb1 = mb0 + 8;
    if (tid < NWARPS * 2)
        mbar_init((unsigned int)__cvta_generic_to_shared(&mbars[tid]), 1);

    if (tid < DD) ts[tid] = tgt[b * DD + tid];
    {
        const int mode = g_mask_mode;
        const size_t mbase = (size_t)b * LL + (size_t)c * CROWS;
        for (int i = tid; i < CROWS; i += NTHREADS) {
            bool v;
            if (mode == 1)      v = ((const unsigned char*)mraw)[mbase + i] != 0;
            else if (mode == 2) v = ((const float*)mraw)[mbase + i] != 0.0f;
            else                v = ((const int*)mraw)[mbase + i] != 0;
            smask[i] = (unsigned char)v;
        }
    }
    __syncthreads();   // mask + mbarrier-init visible

    // --- per-warp tile addressing (linear layout; swizzle moved to q regs) ---
    const int r     = lane & 7;
    const int piece = lane >> 3;
    float4* twarp = tiles + warp * 256;
    const unsigned int tdst0 = (unsigned int)__cvta_generic_to_shared(twarp);
    const unsigned int tdst1 = tdst0 + TILE_BYTES;
    const char* srcb = (const char*)(seq + ((size_t)b * LL + (size_t)c * CROWS + warp * WR) * DD);

    // pre-issue tiles 0 and 1 (overlaps q projection below)
    if (lane == 0) {
        mbar_expect_tx(mb0, TILE_BYTES);
        cp_bulk(tdst0, srcb, TILE_BYTES, mb0);
        mbar_expect_tx(mb1, TILE_BYTES);
        cp_bulk(tdst1, srcb + TILE_BYTES, TILE_BYTES, mb1);
    }

    // --- q projection ---
    if (tid < DD) {
        const float* wr = W + tid * DD;
        float acc = 0.0f;
#pragma unroll
        for (int j = 0; j < DD; j++) acc = fmaf(wr[j], ts[j], acc);
        qs[tid] = acc * 0.125f;     // exact 1/sqrt(64)
    }
    __syncthreads();

    const int i0 = (piece * 4 + 0) ^ r;
    const int i1 = (piece * 4 + 1) ^ r;
    const int i2 = (piece * 4 + 2) ^ r;
    const int i3 = (piece * 4 + 3) ^ r;
    float4 qr0 = ((const float4*)qs)[i0];
    float4 qr1 = ((const float4*)qs)[i1];
    float4 qr2 = ((const float4*)qs)[i2];
    float4 qr3 = ((const float4*)qs)[i3];
    const float4* tb0 = twarp + r * 16;
    const float4* tb1 = twarp + 128 + r * 16;

    int ph0 = 0, ph1 = 0;

    // --- stream loop: wait(t), compute(t), issue(t+2) ---
#pragma unroll 1
    for (int t = 0; t < NTILES; t++) {
        const int buf = t & 1;
        if (buf == 0) { mbar_wait(mb0, ph0); ph0 ^= 1; }
        else          { mbar_wait(mb1, ph1); ph1 ^= 1; }

        const float4* tb = buf ? tb1 : tb0;
        float4 v0 = tb[i0], v1 = tb[i1], v2 = tb[i2], v3 = tb[i3];
        float s = v0.x * qr0.x;
        s = fmaf(v0.y, qr0.y, s); s = fmaf(v0.z, qr0.z, s); s = fmaf(v0.w, qr0.w, s);
        s = fmaf(v1.x, qr1.x, s); s = fmaf(v1.y, qr1.y, s);
        s = fmaf(v1.z, qr1.z, s); s = fmaf(v1.w, qr1.w, s);
        s = fmaf(v2.x, qr2.x, s); s = fmaf(v2.y, qr2.y, s);
        s = fmaf(v2.z, qr2.z, s); s = fmaf(v2.w, qr2.w, s);
        s = fmaf(v3.x, qr3.x, s); s = fmaf(v3.y, qr3.y, s);
        s = fmaf(v3.z, qr3.z, s); s = fmaf(v3.w, qr3.w, s);
        s += __shfl_xor_sync(0xFFFFFFFFu, s, 8);
        s += __shfl_xor_sync(0xFFFFFFFFu, s, 16);
        __syncwarp();

        if (lane < 8) {
            const int lrow = warp * WR + t * 8 + r;
            const int grow = c * CROWS + lrow;
            float sv = smask[lrow] ? s : -1e9f;
            unsigned int fu = __float_as_uint(sv);
            fu = (fu & 0x80000000u) ? ~fu : (fu | 0x80000000u);
            keys[lrow] = ((u64)fu << 32) | (u64)(0xFFFFFFFFu ^ (unsigned)grow);
        }

        if (t + 2 < NTILES && lane == 0) {
            if (buf == 0) { mbar_expect_tx(mb0, TILE_BYTES);
                            cp_bulk(tdst0, srcb + (size_t)(t + 2) * TILE_BYTES, TILE_BYTES, mb0); }
            else          { mbar_expect_tx(mb1, TILE_BYTES);
                            cp_bulk(tdst1, srcb + (size_t)(t + 2) * TILE_BYTES, TILE_BYTES, mb1); }
        }
    }
    __syncwarp();

    // --- warp-local top-64 of 128 (no CTA barriers) ---
    u64* seg = keys + warp * WR;
    for (int k = 2; k <= 64; k <<= 1) {
        for (int j = k >> 1; j > 0; j >>= 1) {
#pragma unroll
            for (int u = 0; u < 2; u++) {
                const int t   = lane + u * 32;          // pair id 0..63
                const int i   = ((t & ~(j - 1)) << 1) | (t & (j - 1));
                const int ixj = i | j;
                u64 a = seg[i], cc = seg[ixj];
                bool desc = ((i & k) == 0);
                if (desc ? (a < cc) : (a > cc)) { seg[i] = cc; seg[ixj] = a; }
            }
            __syncwarp();
        }
    }
    {
        u64 a0 = seg[lane],      c0 = seg[lane + 64];
        u64 a1 = seg[lane + 32], c1 = seg[lane + 96];
        u64 m0 = (a0 > c0) ? a0 : c0;
        u64 m1 = (a1 > c1) ? a1 : c1;
        __syncwarp();
        seg[lane] = m0; seg[lane + 32] = m1;
        __syncwarp();
        for (int j = 32; j > 0; j >>= 1) {
            const int i   = ((lane & ~(j - 1)) << 1) | (lane & (j - 1));
            const int ixj = i | j;
            u64 a = seg[i], cc = seg[ixj];
            if (a < cc) { seg[i] = cc; seg[ixj] = a; }
            __syncwarp();
        }
    }
    __syncthreads();
    // seg[0..63] per warp = its exact top-64, descending.

    // --- CTA merge: 8 desc lists (512 keys) -> 64, in tile buffer ---
    u64* mk = (u64*)tiles;
#pragma unroll
    for (int u = 0; u < 2; u++) {                       // 512 elems / 256 thr
        const int t = tid + u * NTHREADS;
        const int w = t >> 6, i = t & 63;
        const int srci = (w & 1) ? (63 - i) : i;        // odd warps reversed -> asc
        mk[t] = keys[w * WR + srci];
    }
    __syncthreads();
    for (int live = 256; live >= 64; live >>= 1) {
        u64 kp = 0;
        const bool act = tid < live;
        if (act) {
            const int p = tid >> 6, i = tid & 63;
            u64 a = mk[p * 128 + i];
            u64 cc = mk[p * 128 + 64 + i];
            kp = (a > cc) ? a : cc;
        }
        __syncthreads();
        if (act) mk[tid] = kp;
        __syncthreads();
        for (int j = 32; j > 0; j >>= 1) {
            if (tid < live / 2) {
                const int i   = ((tid & ~(j - 1)) << 1) | (tid & (j - 1));
                const int ixj = i | j;
                u64 a = mk[i], cc = mk[ixj];
                bool cdesc = (((i >> 6) & 1) == 0);
                if ((a < cc) == cdesc) { mk[i] = cc; mk[ixj] = a; }
            }
            __syncthreads();
        }
    }

    if (tid < KK) g_part[(size_t)blockIdx.x * KK + tid] = mk[tid];
    __syncthreads();

    // --- fused batch merge: last-arriving chunk-CTA finishes the batch ---
    if (tid == 0) {
        __threadfence();                                 // publish g_part writes
        s_last = (atomicAdd(&g_count[b], 1) == NCHUNK - 1);
    }
    __syncthreads();
    if (!s_last) return;
    __threadfence();                                     // acquire peers' g_part

    u64* sk = keys;                                      // reuse smem (256 keys)
    if (tid < NCHUNK * KK) {
        const int cidx = tid >> 6, i = tid & 63;
        const int srci = (cidx & 1) ? (63 - i) : i;      // odd chunks reversed -> asc
        sk[tid] = g_part[((size_t)b * NCHUNK + cidx) * KK + srci];
    }
    __syncthreads();

    for (int live = 128; live >= 64; live >>= 1) {
        u64 kp = 0;
        const bool act = tid < live;
        if (act) {
            const int p = tid >> 6, i = tid & 63;
            u64 a = sk[p * 128 + i];
            u64 cc = sk[p * 128 + 64 + i];
            kp = (a > cc) ? a : cc;
        }
        __syncthreads();
        if (act) sk[tid] = kp;
        __syncthreads();
        for (int j = 32; j > 0; j >>= 1) {
            if (tid < live / 2) {
                const int i   = ((tid & ~(j - 1)) << 1) | (tid & (j - 1));
                const int ixj = i | j;
                u64 a = sk[i], cc = sk[ixj];
                bool cdesc = (((i >> 6) & 1) == 0);
                if ((a < cc) == cdesc) { sk[i] = cc; sk[ixj] = a; }
            }
            __syncthreads();
        }
    }
    // sk[0..63] = exact global top-64, descending, jax tie-break.

    const float4* seqb4 = (const float4*)(seq + (size_t)b * LL * DD);
    float4* out4 = (float4*)(out_emb + (size_t)b * KK * DD);
#pragma unroll
    for (int u = 0; u < KK * DD / 4 / NTHREADS; u++) {
        const int i   = tid + u * NTHREADS;
        const int kk  = i >> 4;
        const int off = i & 15;
        const int idx = (int)(0xFFFFFFFFu ^ (unsigned int)sk[kk]);
        out4[i] = seqb4[(size_t)idx * (DD / 4) + off];
    }

    if (write_mask && tid < KK) {
        unsigned int fu = (unsigned int)(sk[tid] >> 32);
        unsigned int bits = (fu & 0x80000000u) ? (fu ^ 0x80000000u) : ~fu;
        float s = __uint_as_float(bits);
        out_mask[(size_t)b * KK + tid] = (s > -1e8f) ? 1.0f : 0.0f;
    }

    if (tid == 0) g_count[b] = 0;   // self-reset for next (graph-replayed) launch
}

// ---------------------------------------------------------------------------
extern "C" void kernel_launch(void* const* d_in, const int* in_sizes, int n_in,
                              void* d_out, int out_size)
{
    const float* tgt  = (const float*)d_in[0];
    const float* seq  = (const float*)d_in[2];
    const void*  mask = d_in[4];

    int w_idx = n_in - 1;
    for (int i = n_in - 1; i >= 0; i--) {
        if (in_sizes[i] == DD * DD) { w_idx = i; break; }
    }
    const float* W = (const float*)d_in[w_idx];

    float* out      = (float*)d_out;
    int write_mask  = (out_size >= BB * KK * DD + BB * KK) ? 1 : 0;
    float* out_mask = out + (size_t)BB * KK * DD;

    detect_mask_kernel<<<1, 1024>>>((const unsigned int*)mask);
    gsu_score_kernel<<<BB * NCHUNK, NTHREADS>>>(tgt, seq, mask, W, out, out_mask, write_mask);
}

// round 11
// speedup vs baseline: 1.3008x; 1.3008x over previous
#include <cuda_runtime.h>

#define BB 1024
#define LL 4096
#define DD 64
#define KK 64
#define NCHUNK 4
#define CROWS (LL / NCHUNK)       // 1024 rows per chunk
#define NTHREADS 256
#define NWARPS 8
#define WR (CROWS / NWARPS)       // 128 rows per warp
#define NTILES (WR / 8)           // 16 tiles of 8 rows

typedef unsigned long long u64;

__device__ int g_mask_mode;                 // 0=int32, 1=byte, 2=float32
__device__ u64 g_part[BB * NCHUNK * KK];    // 2 MB chunk-top64 scratch
__device__ int g_count[BB];                 // per-batch arrival counters (self-resetting)

// ---------------------------------------------------------------------------
__global__ void detect_mask_kernel(const unsigned int* __restrict__ m) {
    __shared__ int f_byte, f_float;
    int tid = threadIdx.x;
    if (tid == 0) { f_byte = 0; f_float = 0; }
    __syncthreads();
    unsigned int w = m[tid];
    if (w == 0x3F800000u) f_float = 1;
    else if (w > 1u)      f_byte = 1;
    __syncthreads();
    if (tid == 0) g_mask_mode = f_float ? 2 : (f_byte ? 1 : 0);
}

__device__ __forceinline__ void cp_async16(unsigned int saddr, const void* g) {
    asm volatile("cp.async.cg.shared.global [%0], [%1], 16;" :: "r"(saddr), "l"(g));
}

// compare-exchange: after call, (a,b) ordered desc if d else asc
__device__ __forceinline__ void ce(u64& a, u64& b, bool d) {
    if ((a < b) == d) { u64 t = a; a = b; b = t; }
}

// ---------------------------------------------------------------------------
// Kernel A (fused): one CTA per (batch, chunk). Per-warp cp.async streaming,
// REGISTER-RESIDENT warp top-64 sort (shfl-based), CTA merge -> g_part;
// last-arriving chunk-CTA merges the batch, gathers rows, writes mask.
// ---------------------------------------------------------------------------
__global__ __launch_bounds__(NTHREADS) void gsu_score_kernel(
    const float* __restrict__ tgt,
    const float* __restrict__ seq,
    const void*  __restrict__ mraw,
    const float* __restrict__ W,
    float* __restrict__ out_emb,
    float* __restrict__ out_mask,
    int write_mask)
{
    __shared__ u64 keys[CROWS];                         // 8 KB
    __shared__ float4 tiles[NWARPS * 2 * 128];          // 32 KB (reused as merge buf)
    __shared__ float ts[DD];
    __shared__ float qs[DD];
    __shared__ unsigned char smask[CROWS];              // 1 KB
    __shared__ int s_last;

    const int b   = blockIdx.x >> 2;
    const int c   = blockIdx.x & 3;
    const int tid = threadIdx.x;
    const int lane = tid & 31;
    const int warp = tid >> 5;

    if (tid < DD) ts[tid] = tgt[b * DD + tid];
    {
        const int mode = g_mask_mode;
        const size_t mbase = (size_t)b * LL + (size_t)c * CROWS;
        for (int i = tid; i < CROWS; i += NTHREADS) {
            bool v;
            if (mode == 1)      v = ((const unsigned char*)mraw)[mbase + i] != 0;
            else if (mode == 2) v = ((const float*)mraw)[mbase + i] != 0.0f;
            else                v = ((const int*)mraw)[mbase + i] != 0;
            smask[i] = (unsigned char)v;
        }
    }
    __syncthreads();

    if (tid < DD) {
        const float* wr = W + tid * DD;
        float acc = 0.0f;
#pragma unroll
        for (int j = 0; j < DD; j++) acc = fmaf(wr[j], ts[j], acc);
        qs[tid] = acc * 0.125f;     // exact 1/sqrt(64)
    }
    __syncthreads();

    // --- scoring: per-warp double-buffered cp.async pipeline (R9-proven) ---
    const int r     = lane & 7;
    const int piece = lane >> 3;
    float4 qr[4];
#pragma unroll
    for (int j = 0; j < 4; j++) qr[j] = ((const float4*)qs)[piece * 4 + j];

    const float4* seq4 = (const float4*)(seq + ((size_t)b * LL + (size_t)c * CROWS) * DD);
    float4* twarp = tiles + warp * 256;
    const unsigned int tbase = (unsigned int)__cvta_generic_to_shared(twarp);

    unsigned int dstoff[4];
#pragma unroll
    for (int it = 0; it < 4; it++) {
        const int idx  = it * 32 + lane;
        const int trow = idx >> 4, tcol = idx & 15;
        dstoff[it] = tbase + (unsigned)((trow * 16 + (tcol ^ trow)) << 4);
    }
    const int i0 = (piece * 4 + 0) ^ r;
    const int i1 = (piece * 4 + 1) ^ r;
    const int i2 = (piece * 4 + 2) ^ r;
    const int i3 = (piece * 4 + 3) ^ r;
    const float4* tb0 = twarp + r * 16;
    const float4* tb1 = twarp + 128 + r * 16;
    const float4* src = seq4 + (size_t)(warp * WR) * 16 + lane;

    {
#pragma unroll
        for (int it = 0; it < 4; it++)
            cp_async16(dstoff[it], src + it * 32);
        asm volatile("cp.async.commit_group;");
    }
#pragma unroll 1
    for (int t = 0; t < NTILES; t++) {
        if (t + 1 < NTILES) {
            const unsigned int bufo = ((t + 1) & 1) ? 2048u : 0u;
            const float4* s2 = src + (t + 1) * 128;
#pragma unroll
            for (int it = 0; it < 4; it++)
                cp_async16(dstoff[it] + bufo, s2 + it * 32);
            asm volatile("cp.async.commit_group;");
            asm volatile("cp.async.wait_group 1;");
        } else {
            asm volatile("cp.async.wait_group 0;");
        }
        __syncwarp();

        const float4* tb = (t & 1) ? tb1 : tb0;
        float4 v0 = tb[i0], v1 = tb[i1], v2 = tb[i2], v3 = tb[i3];
        float s = v0.x * qr[0].x;
        s = fmaf(v0.y, qr[0].y, s); s = fmaf(v0.z, qr[0].z, s); s = fmaf(v0.w, qr[0].w, s);
        s = fmaf(v1.x, qr[1].x, s); s = fmaf(v1.y, qr[1].y, s);
        s = fmaf(v1.z, qr[1].z, s); s = fmaf(v1.w, qr[1].w, s);
        s = fmaf(v2.x, qr[2].x, s); s = fmaf(v2.y, qr[2].y, s);
        s = fmaf(v2.z, qr[2].z, s); s = fmaf(v2.w, qr[2].w, s);
        s = fmaf(v3.x, qr[3].x, s); s = fmaf(v3.y, qr[3].y, s);
        s = fmaf(v3.z, qr[3].z, s); s = fmaf(v3.w, qr[3].w, s);
        s += __shfl_xor_sync(0xFFFFFFFFu, s, 8);
        s += __shfl_xor_sync(0xFFFFFFFFu, s, 16);
        __syncwarp();

        if (lane < 8) {
            const int lrow = warp * WR + t * 8 + r;
            const int grow = c * CROWS + lrow;
            float sv = smask[lrow] ? s : -1e9f;
            unsigned int fu = __float_as_uint(sv);
            fu = (fu & 0x80000000u) ? ~fu : (fu | 0x80000000u);
            keys[lrow] = ((u64)fu << 32) | (u64)(0xFFFFFFFFu ^ (unsigned)grow);
        }
    }
    __syncwarp();

    // --- REGISTER warp sort: exact top-64 of 128, sorted desc ---
    u64* seg = keys + warp * WR;
    u64 a0, a1, a2, a3;     // positions 4l .. 4l+3
    {
        ulonglong2 p0 = ((const ulonglong2*)seg)[2 * lane];
        ulonglong2 p1 = ((const ulonglong2*)seg)[2 * lane + 1];
        a0 = p0.x; a1 = p0.y; a2 = p1.x; a3 = p1.y;
    }

    auto xstep = [&](int lmask, bool d) {
        const bool keepmax = (d == ((lane & lmask) == 0));
        u64 o0 = __shfl_xor_sync(0xFFFFFFFFu, a0, lmask);
        u64 o1 = __shfl_xor_sync(0xFFFFFFFFu, a1, lmask);
        u64 o2 = __shfl_xor_sync(0xFFFFFFFFu, a2, lmask);
        u64 o3 = __shfl_xor_sync(0xFFFFFFFFu, a3, lmask);
        if (keepmax) { a0 = a0 > o0 ? a0 : o0; a1 = a1 > o1 ? a1 : o1;
                       a2 = a2 > o2 ? a2 : o2; a3 = a3 > o3 ? a3 : o3; }
        else         { a0 = a0 < o0 ? a0 : o0; a1 = a1 < o1 ? a1 : o1;
                       a2 = a2 < o2 ? a2 : o2; a3 = a3 < o3 ? a3 : o3; }
    };
    auto intra = [&](bool d) {
        ce(a0, a2, d); ce(a1, a3, d);
        ce(a0, a1, d); ce(a2, a3, d);
    };

    ce(a0, a1, true); ce(a2, a3, false);                                   // k=2
    { const bool d = ((lane & 1) == 0);  intra(d); }                       // k=4
    { const bool d = ((lane & 2) == 0);  xstep(1, d); intra(d); }          // k=8
    { const bool d = ((lane & 4) == 0);  xstep(2, d); xstep(1, d); intra(d); }            // k=16
    { const bool d = ((lane & 8) == 0);  xstep(4, d); xstep(2, d); xstep(1, d); intra(d); } // k=32
    { const bool d = ((lane & 16) == 0); xstep(8, d); xstep(4, d); xstep(2, d); xstep(1, d); intra(d); } // k=64
    // positions 0-63 desc (lanes 0-15), 64-127 asc (lanes 16-31)

    {   // compact: top-64 = elementwise max(i, i+64); valid in lanes 0-15
        u64 o0 = __shfl_xor_sync(0xFFFFFFFFu, a0, 16);
        u64 o1 = __shfl_xor_sync(0xFFFFFFFFu, a1, 16);
        u64 o2 = __shfl_xor_sync(0xFFFFFFFFu, a2, 16);
        u64 o3 = __shfl_xor_sync(0xFFFFFFFFu, a3, 16);
        a0 = a0 > o0 ? a0 : o0; a1 = a1 > o1 ? a1 : o1;
        a2 = a2 > o2 ? a2 : o2; a3 = a3 > o3 ? a3 : o3;
    }
    __syncwarp();
    if (lane < 16) {
        ulonglong2 p0; p0.x = a0; p0.y = a1;
        ulonglong2 p1; p1.x = a2; p1.y = a3;
        ((ulonglong2*)seg)[2 * lane]     = p0;
        ((ulonglong2*)seg)[2 * lane + 1] = p1;
    }
    __syncwarp();
    u64 w0, w1;
    {
        ulonglong2 p = ((const ulonglong2*)seg)[lane];   // positions 2l, 2l+1
        w0 = p.x; w1 = p.y;
    }
    auto mstep = [&](int lmask) {
        const bool keepmax = ((lane & lmask) == 0);
        u64 o0 = __shfl_xor_sync(0xFFFFFFFFu, w0, lmask);
        u64 o1 = __shfl_xor_sync(0xFFFFFFFFu, w1, lmask);
        if (keepmax) { w0 = w0 > o0 ? w0 : o0; w1 = w1 > o1 ? w1 : o1; }
        else         { w0 = w0 < o0 ? w0 : o0; w1 = w1 < o1 ? w1 : o1; }
    };
    mstep(16); mstep(8); mstep(4); mstep(2); mstep(1);
    ce(w0, w1, true);
    {
        ulonglong2 p; p.x = w0; p.y = w1;
        ((ulonglong2*)seg)[lane] = p;                    // seg[0..63] sorted desc
    }
    __syncthreads();

    // --- CTA merge: 8 desc lists (512 keys) -> 64, in tile buffer ---
    u64* mk = (u64*)tiles;
#pragma unroll
    for (int u = 0; u < 2; u++) {
        const int t = tid + u * NTHREADS;
        const int w = t >> 6, i = t & 63;
        const int srci = (w & 1) ? (63 - i) : i;
        mk[t] = keys[w * WR + srci];
    }
    __syncthreads();
    for (int live = 256; live >= 64; live >>= 1) {
        u64 kp = 0;
        const bool act = tid < live;
        if (act) {
            const int p = tid >> 6, i = tid & 63;
            u64 a = mk[p * 128 + i];
            u64 cc = mk[p * 128 + 64 + i];
            kp = (a > cc) ? a : cc;
        }
        __syncthreads();
        if (act) mk[tid] = kp;
        __syncthreads();
        for (int j = 32; j > 0; j >>= 1) {
            if (tid < live / 2) {
                const int i   = ((tid & ~(j - 1)) << 1) | (tid & (j - 1));
                const int ixj = i | j;
                u64 a = mk[i], cc = mk[ixj];
                bool cdesc = (((i >> 6) & 1) == 0);
                if ((a < cc) == cdesc) { mk[i] = cc; mk[ixj] = a; }
            }
            __syncthreads();
        }
    }

    if (tid < KK) g_part[(size_t)blockIdx.x * KK + tid] = mk[tid];
    __syncthreads();

    // --- fused batch merge: last-arriving chunk-CTA finishes the batch ---
    if (tid == 0) {
        __threadfence();
        s_last = (atomicAdd(&g_count[b], 1) == NCHUNK - 1);
    }
    __syncthreads();
    if (!s_last) return;
    __threadfence();

    u64* sk = keys;
    if (tid < NCHUNK * KK) {
        const int cidx = tid >> 6, i = tid & 63;
        const int srci = (cidx & 1) ? (63 - i) : i;
        sk[tid] = g_part[((size_t)b * NCHUNK + cidx) * KK + srci];
    }
    __syncthreads();

    for (int live = 128; live >= 64; live >>= 1) {
        u64 kp = 0;
        const bool act = tid < live;
        if (act) {
            const int p = tid >> 6, i = tid & 63;
            u64 a = sk[p * 128 + i];
            u64 cc = sk[p * 128 + 64 + i];
            kp = (a > cc) ? a : cc;
        }
        __syncthreads();
        if (act) sk[tid] = kp;
        __syncthreads();
        for (int j = 32; j > 0; j >>= 1) {
            if (tid < live / 2) {
                const int i   = ((tid & ~(j - 1)) << 1) | (tid & (j - 1));
                const int ixj = i | j;
                u64 a = sk[i], cc = sk[ixj];
                bool cdesc = (((i >> 6) & 1) == 0);
                if ((a < cc) == cdesc) { sk[i] = cc; sk[ixj] = a; }
            }
            __syncthreads();
        }
    }

    const float4* seqb4 = (const float4*)(seq + (size_t)b * LL * DD);
    float4* out4 = (float4*)(out_emb + (size_t)b * KK * DD);
#pragma unroll
    for (int u = 0; u < KK * DD / 4 / NTHREADS; u++) {
        const int i   = tid + u * NTHREADS;
        const int kk  = i >> 4;
        const int off = i & 15;
        const int idx = (int)(0xFFFFFFFFu ^ (unsigned int)sk[kk]);
        out4[i] = seqb4[(size_t)idx * (DD / 4) + off];
    }

    if (write_mask && tid < KK) {
        unsigned int fu = (unsigned int)(sk[tid] >> 32);
        unsigned int bits = (fu & 0x80000000u) ? (fu ^ 0x80000000u) : ~fu;
        float s = __uint_as_float(bits);
        out_mask[(size_t)b * KK + tid] = (s > -1e8f) ? 1.0f : 0.0f;
    }

    if (tid == 0) g_count[b] = 0;
}

// ---------------------------------------------------------------------------
extern "C" void kernel_launch(void* const* d_in, const int* in_sizes, int n_in,
                              void* d_out, int out_size)
{
    const float* tgt  = (const float*)d_in[0];
    const float* seq  = (const float*)d_in[2];
    const void*  mask = d_in[4];

    int w_idx = n_in - 1;
    for (int i = n_in - 1; i >= 0; i--) {
        if (in_sizes[i] == DD * DD) { w_idx = i; break; }
    }
    const float* W = (const float*)d_in[w_idx];

    float* out      = (float*)d_out;
    int write_mask  = (out_size >= BB * KK * DD + BB * KK) ? 1 : 0;
    float* out_mask = out + (size_t)BB * KK * DD;

    detect_mask_kernel<<<1, 1024>>>((const unsigned int*)mask);
    gsu_score_kernel<<<BB * NCHUNK, NTHREADS>>>(tgt, seq, mask, W, out, out_mask, write_mask);
}

// round 12
// speedup vs baseline: 1.3633x; 1.0481x over previous
#include <cuda_runtime.h>

#define BB 1024
#define LL 4096
#define DD 64
#define KK 64
#define NCHUNK 4
#define CROWS (LL / NCHUNK)       // 1024 rows per chunk
#define NTHREADS 256
#define NWARPS 8
#define WR (CROWS / NWARPS)       // 128 rows per warp
#define NTILES (WR / 8)           // 16 tiles of 8 rows

typedef unsigned long long u64;

__device__ int g_mask_mode;                 // 0=int32, 1=byte, 2=float32
__device__ u64 g_part[BB * NCHUNK * KK];    // 2 MB chunk-top64 scratch
__device__ int g_count[BB];                 // per-batch arrival counters (self-resetting)

// ---------------------------------------------------------------------------
__global__ void detect_mask_kernel(const unsigned int* __restrict__ m) {
    __shared__ int f_byte, f_float;
    int tid = threadIdx.x;
    if (tid == 0) { f_byte = 0; f_float = 0; }
    __syncthreads();
    unsigned int w = m[tid];
    if (w == 0x3F800000u) f_float = 1;
    else if (w > 1u)      f_byte = 1;
    __syncthreads();
    if (tid == 0) g_mask_mode = f_float ? 2 : (f_byte ? 1 : 0);
}

__device__ __forceinline__ void cp_async16(unsigned int saddr, const void* g) {
    asm volatile("cp.async.cg.shared.global [%0], [%1], 16;" :: "r"(saddr), "l"(g));
}

// compare-exchange: after call, (a,b) ordered desc if d else asc
__device__ __forceinline__ void ce(u64& a, u64& b, bool d) {
    if ((a < b) == d) { u64 t = a; a = b; b = t; }
}

// ---------------------------------------------------------------------------
// Kernel A (fused): one CTA per (batch, chunk). Per-warp cp.async streaming,
// ballot-register mask, register-resident warp top-64 sort, CTA merge ->
// g_part; last-arriving chunk-CTA merges the batch, gathers rows, writes mask.
// ---------------------------------------------------------------------------
__global__ __launch_bounds__(NTHREADS, 5) void gsu_score_kernel(
    const float* __restrict__ tgt,
    const float* __restrict__ seq,
    const void*  __restrict__ mraw,
    const float* __restrict__ W,
    float* __restrict__ out_emb,
    float* __restrict__ out_mask,
    int write_mask)
{
    __shared__ u64 keys[CROWS];                         // 8 KB
    __shared__ float4 tiles[NWARPS * 2 * 128];          // 32 KB (reused as merge buf)
    __shared__ float ts[DD];
    __shared__ float qs[DD];
    __shared__ int s_last;

    const int b   = blockIdx.x >> 2;
    const int c   = blockIdx.x & 3;
    const int tid = threadIdx.x;
    const int lane = tid & 31;
    const int warp = tid >> 5;

    // --- mask -> ballot words -> per-thread mask register (no smem) ---
    // Lane l loads rows 4l..4l+3 of this warp's 128-row segment; ballot wj
    // holds (bit l) = validity of row 4l+j. Writer of row m = t*8+r reads
    // word (r&3), bit (2t + (r>>2)).
    unsigned int mymask;
    {
        const int mode = g_mask_mode;
        const size_t mi = (size_t)b * LL + (size_t)c * CROWS + warp * WR + lane * 4;
        bool b0, b1, b2, b3;
        if (mode == 1) {
            uchar4 v = *(const uchar4*)((const unsigned char*)mraw + mi);
            b0 = v.x != 0; b1 = v.y != 0; b2 = v.z != 0; b3 = v.w != 0;
        } else if (mode == 2) {
            float4 v = *(const float4*)((const float*)mraw + mi);
            b0 = v.x != 0.0f; b1 = v.y != 0.0f; b2 = v.z != 0.0f; b3 = v.w != 0.0f;
        } else {
            int4 v = *(const int4*)((const int*)mraw + mi);
            b0 = v.x != 0; b1 = v.y != 0; b2 = v.z != 0; b3 = v.w != 0;
        }
        unsigned int w0 = __ballot_sync(0xFFFFFFFFu, b0);
        unsigned int w1 = __ballot_sync(0xFFFFFFFFu, b1);
        unsigned int w2 = __ballot_sync(0xFFFFFFFFu, b2);
        unsigned int w3 = __ballot_sync(0xFFFFFFFFu, b3);
        const int j = lane & 3;   // == r&3 for lanes<8 consumers; harmless otherwise
        mymask = (j == 0) ? w0 : (j == 1) ? w1 : (j == 2) ? w2 : w3;
    }

    if (tid < DD) ts[tid] = tgt[b * DD + tid];
    __syncthreads();
    if (tid < DD) {
        const float* wr = W + tid * DD;
        float acc = 0.0f;
#pragma unroll
        for (int j = 0; j < DD; j++) acc = fmaf(wr[j], ts[j], acc);
        qs[tid] = acc * 0.125f;     // exact 1/sqrt(64)
    }
    __syncthreads();

    // --- scoring: per-warp double-buffered cp.async pipeline (proven) ---
    const int r     = lane & 7;
    const int piece = lane >> 3;
    float4 qr[4];
#pragma unroll
    for (int j = 0; j < 4; j++) qr[j] = ((const float4*)qs)[piece * 4 + j];

    const float4* seq4 = (const float4*)(seq + ((size_t)b * LL + (size_t)c * CROWS) * DD);
    float4* twarp = tiles + warp * 256;
    const unsigned int tbase = (unsigned int)__cvta_generic_to_shared(twarp);

    unsigned int dstoff[4];
#pragma unroll
    for (int it = 0; it < 4; it++) {
        const int idx  = it * 32 + lane;
        const int trow = idx >> 4, tcol = idx & 15;
        dstoff[it] = tbase + (unsigned)((trow * 16 + (tcol ^ trow)) << 4);
    }
    const int i0 = (piece * 4 + 0) ^ r;
    const int i1 = (piece * 4 + 1) ^ r;
    const int i2 = (piece * 4 + 2) ^ r;
    const int i3 = (piece * 4 + 3) ^ r;
    const float4* tb0 = twarp + r * 16;
    const float4* tb1 = twarp + 128 + r * 16;
    const float4* src = seq4 + (size_t)(warp * WR) * 16 + lane;
    const unsigned int shbase = (unsigned)(r >> 2);

    {
#pragma unroll
        for (int it = 0; it < 4; it++)
            cp_async16(dstoff[it], src + it * 32);
        asm volatile("cp.async.commit_group;");
    }
#pragma unroll 1
    for (int t = 0; t < NTILES; t++) {
        if (t + 1 < NTILES) {
            const unsigned int bufo = ((t + 1) & 1) ? 2048u : 0u;
            const float4* s2 = src + (t + 1) * 128;
#pragma unroll
            for (int it = 0; it < 4; it++)
                cp_async16(dstoff[it] + bufo, s2 + it * 32);
            asm volatile("cp.async.commit_group;");
            asm volatile("cp.async.wait_group 1;");
        } else {
            asm volatile("cp.async.wait_group 0;");
        }
        __syncwarp();

        const float4* tb = (t & 1) ? tb1 : tb0;
        float4 v0 = tb[i0], v1 = tb[i1], v2 = tb[i2], v3 = tb[i3];
        float s = v0.x * qr[0].x;
        s = fmaf(v0.y, qr[0].y, s); s = fmaf(v0.z, qr[0].z, s); s = fmaf(v0.w, qr[0].w, s);
        s = fmaf(v1.x, qr[1].x, s); s = fmaf(v1.y, qr[1].y, s);
        s = fmaf(v1.z, qr[1].z, s); s = fmaf(v1.w, qr[1].w, s);
        s = fmaf(v2.x, qr[2].x, s); s = fmaf(v2.y, qr[2].y, s);
        s = fmaf(v2.z, qr[2].z, s); s = fmaf(v2.w, qr[2].w, s);
        s = fmaf(v3.x, qr[3].x, s); s = fmaf(v3.y, qr[3].y, s);
        s = fmaf(v3.z, qr[3].z, s); s = fmaf(v3.w, qr[3].w, s);
        s += __shfl_xor_sync(0xFFFFFFFFu, s, 8);
        s += __shfl_xor_sync(0xFFFFFFFFu, s, 16);
        __syncwarp();

        if (lane < 8) {
            const int lrow = warp * WR + t * 8 + r;
            const int grow = c * CROWS + lrow;
            const bool valid = (mymask >> (2 * t + shbase)) & 1u;
            float sv = valid ? s : -1e9f;
            unsigned int fu = __float_as_uint(sv);
            fu = (fu & 0x80000000u) ? ~fu : (fu | 0x80000000u);
            keys[lrow] = ((u64)fu << 32) | (u64)(0xFFFFFFFFu ^ (unsigned)grow);
        }
    }
    __syncwarp();

    // --- REGISTER warp sort: exact top-64 of 128, sorted desc ---
    u64* seg = keys + warp * WR;
    u64 a0, a1, a2, a3;     // positions 4l .. 4l+3
    {
        ulonglong2 p0 = ((const ulonglong2*)seg)[2 * lane];
        ulonglong2 p1 = ((const ulonglong2*)seg)[2 * lane + 1];
        a0 = p0.x; a1 = p0.y; a2 = p1.x; a3 = p1.y;
    }

    auto xstep = [&](int lmask, bool d) {
        const bool keepmax = (d == ((lane & lmask) == 0));
        u64 o0 = __shfl_xor_sync(0xFFFFFFFFu, a0, lmask);
        u64 o1 = __shfl_xor_sync(0xFFFFFFFFu, a1, lmask);
        u64 o2 = __shfl_xor_sync(0xFFFFFFFFu, a2, lmask);
        u64 o3 = __shfl_xor_sync(0xFFFFFFFFu, a3, lmask);
        if (keepmax) { a0 = a0 > o0 ? a0 : o0; a1 = a1 > o1 ? a1 : o1;
                       a2 = a2 > o2 ? a2 : o2; a3 = a3 > o3 ? a3 : o3; }
        else         { a0 = a0 < o0 ? a0 : o0; a1 = a1 < o1 ? a1 : o1;
                       a2 = a2 < o2 ? a2 : o2; a3 = a3 < o3 ? a3 : o3; }
    };
    auto intra = [&](bool d) {
        ce(a0, a2, d); ce(a1, a3, d);
        ce(a0, a1, d); ce(a2, a3, d);
    };

    ce(a0, a1, true); ce(a2, a3, false);                                   // k=2
    { const bool d = ((lane & 1) == 0);  intra(d); }                       // k=4
    { const bool d = ((lane & 2) == 0);  xstep(1, d); intra(d); }          // k=8
    { const bool d = ((lane & 4) == 0);  xstep(2, d); xstep(1, d); intra(d); }            // k=16
    { const bool d = ((lane & 8) == 0);  xstep(4, d); xstep(2, d); xstep(1, d); intra(d); } // k=32
    { const bool d = ((lane & 16) == 0); xstep(8, d); xstep(4, d); xstep(2, d); xstep(1, d); intra(d); } // k=64
    // positions 0-63 desc (lanes 0-15), 64-127 asc (lanes 16-31)

    {   // compact: top-64 = elementwise max(i, i+64); valid in lanes 0-15
        u64 o0 = __shfl_xor_sync(0xFFFFFFFFu, a0, 16);
        u64 o1 = __shfl_xor_sync(0xFFFFFFFFu, a1, 16);
        u64 o2 = __shfl_xor_sync(0xFFFFFFFFu, a2, 16);
        u64 o3 = __shfl_xor_sync(0xFFFFFFFFu, a3, 16);
        a0 = a0 > o0 ? a0 : o0; a1 = a1 > o1 ? a1 : o1;
        a2 = a2 > o2 ? a2 : o2; a3 = a3 > o3 ? a3 : o3;
    }
    __syncwarp();
    if (lane < 16) {
        ulonglong2 p0; p0.x = a0; p0.y = a1;
        ulonglong2 p1; p1.x = a2; p1.y = a3;
        ((ulonglong2*)seg)[2 * lane]     = p0;
        ((ulonglong2*)seg)[2 * lane + 1] = p1;
    }
    __syncwarp();
    u64 w0, w1;
    {
        ulonglong2 p = ((const ulonglong2*)seg)[lane];   // positions 2l, 2l+1
        w0 = p.x; w1 = p.y;
    }
    auto mstep = [&](int lmask) {
        const bool keepmax = ((lane & lmask) == 0);
        u64 o0 = __shfl_xor_sync(0xFFFFFFFFu, w0, lmask);
        u64 o1 = __shfl_xor_sync(0xFFFFFFFFu, w1, lmask);
        if (keepmax) { w0 = w0 > o0 ? w0 : o0; w1 = w1 > o1 ? w1 : o1; }
        else         { w0 = w0 < o0 ? w0 : o0; w1 = w1 < o1 ? w1 : o1; }
    };
    mstep(16); mstep(8); mstep(4); mstep(2); mstep(1);
    ce(w0, w1, true);
    {
        ulonglong2 p; p.x = w0; p.y = w1;
        ((ulonglong2*)seg)[lane] = p;                    // seg[0..63] sorted desc
    }
    __syncthreads();

    // --- CTA merge: 8 desc lists (512 keys) -> 64, in tile buffer ---
    u64* mk = (u64*)tiles;
#pragma unroll
    for (int u = 0; u < 2; u++) {
        const int t = tid + u * NTHREADS;
        const int w = t >> 6, i = t & 63;
        const int srci = (w & 1) ? (63 - i) : i;
        mk[t] = keys[w * WR + srci];
    }
    __syncthreads();
    for (int live = 256; live >= 64; live >>= 1) {
        u64 kp = 0;
        const bool act = tid < live;
        if (act) {
            const int p = tid >> 6, i = tid & 63;
            u64 a = mk[p * 128 + i];
            u64 cc = mk[p * 128 + 64 + i];
            kp = (a > cc) ? a : cc;
        }
        __syncthreads();
        if (act) mk[tid] = kp;
        __syncthreads();
        for (int j = 32; j > 0; j >>= 1) {
            if (tid < live / 2) {
                const int i   = ((tid & ~(j - 1)) << 1) | (tid & (j - 1));
                const int ixj = i | j;
                u64 a = mk[i], cc = mk[ixj];
                bool cdesc = (((i >> 6) & 1) == 0);
                if ((a < cc) == cdesc) { mk[i] = cc; mk[ixj] = a; }
            }
            __syncthreads();
        }
    }

    if (tid < KK) g_part[(size_t)blockIdx.x * KK + tid] = mk[tid];
    __syncthreads();

    // --- fused batch merge: last-arriving chunk-CTA finishes the batch ---
    if (tid == 0) {
        __threadfence();
        s_last = (atomicAdd(&g_count[b], 1) == NCHUNK - 1);
    }
    __syncthreads();
    if (!s_last) return;
    __threadfence();

    u64* sk = keys;
    if (tid < NCHUNK * KK) {
        const int cidx = tid >> 6, i = tid & 63;
        const int srci = (cidx & 1) ? (63 - i) : i;
        sk[tid] = g_part[((size_t)b * NCHUNK + cidx) * KK + srci];
    }
    __syncthreads();

    for (int live = 128; live >= 64; live >>= 1) {
        u64 kp = 0;
        const bool act = tid < live;
        if (act) {
            const int p = tid >> 6, i = tid & 63;
            u64 a = sk[p * 128 + i];
            u64 cc = sk[p * 128 + 64 + i];
            kp = (a > cc) ? a : cc;
        }
        __syncthreads();
        if (act) sk[tid] = kp;
        __syncthreads();
        for (int j = 32; j > 0; j >>= 1) {
            if (tid < live / 2) {
                const int i   = ((tid & ~(j - 1)) << 1) | (tid & (j - 1));
                const int ixj = i | j;
                u64 a = sk[i], cc = sk[ixj];
                bool cdesc = (((i >> 6) & 1) == 0);
                if ((a < cc) == cdesc) { sk[i] = cc; sk[ixj] = a; }
            }
            __syncthreads();
        }
    }

    const float4* seqb4 = (const float4*)(seq + (size_t)b * LL * DD);
    float4* out4 = (float4*)(out_emb + (size_t)b * KK * DD);
#pragma unroll
    for (int u = 0; u < KK * DD / 4 / NTHREADS; u++) {
        const int i   = tid + u * NTHREADS;
        const int kk  = i >> 4;
        const int off = i & 15;
        const int idx = (int)(0xFFFFFFFFu ^ (unsigned int)sk[kk]);
        out4[i] = seqb4[(size_t)idx * (DD / 4) + off];
    }

    if (write_mask && tid < KK) {
        unsigned int fu = (unsigned int)(sk[tid] >> 32);
        unsigned int bits = (fu & 0x80000000u) ? (fu ^ 0x80000000u) : ~fu;
        float s = __uint_as_float(bits);
        out_mask[(size_t)b * KK + tid] = (s > -1e8f) ? 1.0f : 0.0f;
    }

    if (tid == 0) g_count[b] = 0;
}

// ---------------------------------------------------------------------------
extern "C" void kernel_launch(void* const* d_in, const int* in_sizes, int n_in,
                              void* d_out, int out_size)
{
    const float* tgt  = (const float*)d_in[0];
    const float* seq  = (const float*)d_in[2];
    const void*  mask = d_in[4];

    int w_idx = n_in - 1;
    for (int i = n_in - 1; i >= 0; i--) {
        if (in_sizes[i] == DD * DD) { w_idx = i; break; }
    }
    const float* W = (const float*)d_in[w_idx];

    float* out      = (float*)d_out;
    int write_mask  = (out_size >= BB * KK * DD + BB * KK) ? 1 : 0;
    float* out_mask = out + (size_t)BB * KK * DD;

    detect_mask_kernel<<<1, 1024>>>((const unsigned int*)mask);
    gsu_score_kernel<<<BB * NCHUNK, NTHREADS>>>(tgt, seq, mask, W, out, out_mask, write_mask);
}